// round 8
// baseline (speedup 1.0000x reference)
#include <cuda_runtime.h>

#define N_FULL   50000
#define NLAT     10
#define MU       32
#define BATCH    8
#define NODES    32
#define MSTR     33               // m-stride in G/W2 (and row stride in P2)
#define ISTR     1058             // i-stride = 32*33+2 (mod 32 == 2)
#define GSZ      (NLAT * ISTR)    // 10580 floats per array
#define TMAIN    512

// Scratch (static __device__ arrays: no dynamic allocation allowed)
__device__ float g_encoded[BATCH * NLAT];                 // bias pre-added
__device__ __align__(128) float g_dec4[N_FULL * 16];      // 64B rows [v0..v9,pad6]

// ---------------------------------------------------------------------------
// Kernel 1 (fused): blocks 0..79 compute encoded[b,i] + enc_b[i] directly.
// Blocks 80..275 transpose decoder [n,N] -> [N,16] (64B-aligned rows).
// ---------------------------------------------------------------------------
__global__ void __launch_bounds__(256)
prep_encode_kernel(const float* __restrict__ x,
                   const float* __restrict__ ew,
                   const float* __restrict__ enc_b,
                   const float* __restrict__ decoder) {
    if (blockIdx.x < BATCH * NLAT) {
        const int b = blockIdx.x / NLAT;
        const int i = blockIdx.x % NLAT;
        const float4* xr = (const float4*)(x  + (size_t)b * N_FULL);
        const float4* wr = (const float4*)(ew + (size_t)i * N_FULL);
        float acc = 0.0f;
        for (int t = threadIdx.x; t < N_FULL / 4; t += 256) {
            float4 a = __ldg(xr + t);
            float4 c = __ldg(wr + t);
            acc = fmaf(a.x, c.x, acc);
            acc = fmaf(a.y, c.y, acc);
            acc = fmaf(a.z, c.z, acc);
            acc = fmaf(a.w, c.w, acc);
        }
#pragma unroll
        for (int d = 16; d > 0; d >>= 1)
            acc += __shfl_xor_sync(0xffffffffu, acc, d);
        __shared__ float red[8];
        int lane = threadIdx.x & 31, warp = threadIdx.x >> 5;
        if (lane == 0) red[warp] = acc;
        __syncthreads();
        if (threadIdx.x == 0) {
            float s = 0.0f;
#pragma unroll
            for (int w = 0; w < 8; w++) s += red[w];
            g_encoded[blockIdx.x] = s + __ldg(enc_b + i);   // bias folded in
        }
    } else {
        int p = (blockIdx.x - BATCH * NLAT) * 256 + threadIdx.x;
        if (p < N_FULL) {
            float v[NLAT];
#pragma unroll
            for (int i = 0; i < NLAT; i++)
                v[i] = __ldg(decoder + (size_t)i * N_FULL + p);
            float4* dst = (float4*)(g_dec4 + (size_t)p * 16);
            dst[0] = make_float4(v[0], v[1], v[2], v[3]);
            dst[1] = make_float4(v[4], v[5], v[6], v[7]);
            dst[2] = make_float4(v[8], v[9], 0.0f, 0.0f);
            dst[3] = make_float4(0.0f, 0.0f, 0.0f, 0.0f);
        }
    }
}

// ---------------------------------------------------------------------------
// Kernel 2: main. 512 threads (16 warps), 32 nodes/block, 2 CTAs/SM.
//
//  Entry: warps 0..9 PREFETCH their 10 bw values into registers (bw is an
//    input, so this precedes the PDL grid sync); latency hidden behind
//    gather + scan, consumed two barriers later.
//  Phase A (gather): 4 lanes per 64B decoder row; one warp-LDG = 8 random
//    rows = 8 line-touches -> 1 L1 wavefront per neighbour row.
//    Scatter banks (8q+2u+m+j)%32: conflict-free.
//  Phase B (scan): warps 0..9, task (i=warp, j=lane): G <- prefix(g),
//    W2 <- prefix(m^2 g) over m. Banks (2i+m+j)%32: conflict-free.
//  Phase C: warp = i (10 warps), lane = j. z[b] = sum_k bwv[k]*enc[k][b]
//    computed ONCE per (i,p) for all 8 batches (enc via broadcast LDS.128
//    from smem tile) -> 100 bw LDG/CTA instead of 800. Closed-form window:
//      smoothed = (Pg[cnt-1] - inv2*Pm2[cnt-1]) / (cnt - inv2*S2(cnt));
//    contribution enc[b,i]*smv parked in P2[b][i][j].
//  Combine: warps 0..7 (b = warp) sum P2 over i, store out[b,p].
// ---------------------------------------------------------------------------
__global__ void __launch_bounds__(TMAIN, 2)
main_kernel(const float* __restrict__ bw,
            const int*   __restrict__ neigh,
            float*       __restrict__ out) {
    extern __shared__ float sm[];
    float*          G    = sm;                         // [GSZ]
    float*          W2   = sm + GSZ;                   // [GSZ]
    float*          P2   = sm + 2 * GSZ;               // [8][10][33]
    float*          encS = P2 + BATCH * NLAT * MSTR;   // [10][8]  (k-major)
    unsigned short* NB   = (unsigned short*)(encS + BATCH * NLAT);  // [1024]

    const int tid    = threadIdx.x;
    const int lane   = tid & 31;
    const int warp   = tid >> 5;
    const int p_base = blockIdx.x * NODES;
    const int p      = p_base + lane;
    const int pc     = (p < N_FULL) ? p : (N_FULL - 1);

    // ---- inputs only: neighbour tile + bw prefetch BEFORE the PDL sync ----
    {
        int base = p_base * MU + tid * 2;
        int2 v = make_int2(0, 0);
        if (base + 1 < N_FULL * MU) v = *(const int2*)(neigh + base);
        NB[tid * 2 + 0] = (unsigned short)v.x;
        NB[tid * 2 + 1] = (unsigned short)v.y;
    }
    float bwv[NLAT];                     // bw[i=warp, k, pc], warps 0..9
    if (warp < NLAT) {
#pragma unroll
        for (int k = 0; k < NLAT; k++)
            bwv[k] = __ldg(bw + (size_t)(warp * NLAT + k) * N_FULL + pc);
    }
#if defined(__CUDA_ARCH__) && (__CUDA_ARCH__ >= 900)
    cudaGridDependencySynchronize();     // wait for prep_encode results
#endif
    // encoded tile -> smem, k-major: encS[k*8+b]
    if (tid < BATCH * NLAT)
        encS[tid] = g_encoded[(tid & 7) * NLAT + (tid >> 3)];
    __syncthreads();

    // ---- Phase A: cooperative gather (64 rows/warp, 8 rows per LDG) ----
    {
        const int q  = lane & 3;         // 16B quarter of the 64B row
        const int rl = lane >> 2;        // row-in-instruction 0..7
#pragma unroll
        for (int t = 0; t < 8; t++) {
            const int r = warp * 64 + t * 8 + rl;   // flat row: j=r>>5, m=r&31
            const int m = r & 31;
            const int j = r >> 5;
            const int nb = NB[r];
            if (q < 3) {
                float4 v = __ldg((const float4*)g_dec4 + nb * 4 + q);
                const int a0 = (4 * q) * ISTR + m * MSTR + j;
                G[a0] = v.x;
                G[a0 + ISTR] = v.y;
                if (q < 2) {
                    G[a0 + 2 * ISTR] = v.z;
                    G[a0 + 3 * ISTR] = v.w;
                }
            }
        }
    }
    __syncthreads();

    // ---- Phase B: inclusive prefix over m (warps 0..9: i = warp, j = lane)
    if (tid < NLAT * NODES) {
        const int base = warp * ISTR + lane;
        float pg = 0.0f, pm = 0.0f;
#pragma unroll
        for (int m = 0; m < MU; m++) {
            float v = G[base + m * MSTR];
            pg += v;
            pm = fmaf((float)(m * m), v, pm);
            G [base + m * MSTR] = pg;
            W2[base + m * MSTR] = pm;
        }
    }
    __syncthreads();

    // ---- Phase C: warp = i, lane = j; all 8 batches per thread ----
    if (warp < NLAT) {
        const int i = warp;
        const int j = lane;

        float z[BATCH];
#pragma unroll
        for (int b = 0; b < BATCH; b++) z[b] = 0.0f;
#pragma unroll
        for (int k = 0; k < NLAT; k++) {
            float4 e0 = *(const float4*)(encS + k * 8);      // broadcast LDS
            float4 e1 = *(const float4*)(encS + k * 8 + 4);
            z[0] = fmaf(bwv[k], e0.x, z[0]);
            z[1] = fmaf(bwv[k], e0.y, z[1]);
            z[2] = fmaf(bwv[k], e0.z, z[2]);
            z[3] = fmaf(bwv[k], e0.w, z[3]);
            z[4] = fmaf(bwv[k], e1.x, z[4]);
            z[5] = fmaf(bwv[k], e1.y, z[5]);
            z[6] = fmaf(bwv[k], e1.z, z[6]);
            z[7] = fmaf(bwv[k], e1.w, z[7]);
        }

#pragma unroll
        for (int b = 0; b < BATCH; b++) {
            float e    = __expf(-z[b]);
            float tt   = 1.0f + e;                              // = 1/w
            float u    = __fdividef((float)MU, tt);             // = MU*w
            int   cnt  = min(MU, (int)u + 1);                   // #active m
            float inv2 = tt * tt * (1.0f / (float)(MU * MU));   // 1/(MU*w)^2

            const int base = i * ISTR + (cnt - 1) * MSTR + j;
            float Pg = G[base];
            float Pm = W2[base];
            int   c1 = cnt - 1;
            float S2 = (float)(c1 * cnt * (2 * cnt - 1)) * (1.0f / 6.0f);
            float s  = (float)cnt - inv2 * S2;
            float smv = __fdividef(fmaf(-inv2, Pm, Pg), s);
            P2[(b * NLAT + i) * MSTR + j] = encS[i * 8 + b] * smv;
        }
    }
    __syncthreads();

    // ---- Combine: warp = b (8 warps), lane = j: sum over i, store ----
    if (warp < BATCH && p < N_FULL) {
        float acc = 0.0f;
#pragma unroll
        for (int i = 0; i < NLAT; i++)
            acc += P2[(warp * NLAT + i) * MSTR + lane];
        out[(size_t)warp * N_FULL + p] = acc;
    }
}

// ---------------------------------------------------------------------------
extern "C" void kernel_launch(void* const* d_in, const int* in_sizes, int n_in,
                              void* d_out, int out_size) {
    const float* x       = (const float*)d_in[0];
    const float* enc_w   = (const float*)d_in[1];
    const float* enc_b   = (const float*)d_in[2];
    const float* decoder = (const float*)d_in[3];
    const float* bw      = (const float*)d_in[4];
    const int*   neigh   = (const int*)  d_in[5];
    float*       out     = (float*)d_out;
    (void)in_sizes; (void)n_in; (void)out_size;

    const int tp_blocks = (N_FULL + 255) / 256;                 // 196
    prep_encode_kernel<<<BATCH * NLAT + tp_blocks, 256>>>(x, enc_w, enc_b,
                                                          decoder);

    size_t smem_bytes = (size_t)(2 * GSZ + BATCH * NLAT * MSTR + BATCH * NLAT)
                        * sizeof(float)
                      + (size_t)(NODES * MU) * sizeof(unsigned short);
    cudaFuncSetAttribute(main_kernel,
                         cudaFuncAttributeMaxDynamicSharedMemorySize,
                         (int)smem_bytes);

    // main with PDL: overlap its prologue with prep_encode execution
    cudaLaunchConfig_t cfg = {};
    cfg.gridDim  = dim3((N_FULL + NODES - 1) / NODES);   // 1563
    cfg.blockDim = dim3(TMAIN);
    cfg.dynamicSmemBytes = smem_bytes;
    cfg.stream = 0;
    cudaLaunchAttribute attr[1];
    attr[0].id = cudaLaunchAttributeProgrammaticStreamSerialization;
    attr[0].val.programmaticStreamSerializationAllowed = 1;
    cfg.attrs = attr;
    cfg.numAttrs = 1;
    if (cudaLaunchKernelEx(&cfg, main_kernel, bw, neigh, out) != cudaSuccess) {
        main_kernel<<<(N_FULL + NODES - 1) / NODES, TMAIN, smem_bytes>>>(
            bw, neigh, out);
    }
}

// round 9
// speedup vs baseline: 1.0899x; 1.0899x over previous
#include <cuda_runtime.h>

#define N_FULL   50000
#define NLAT     10
#define MU       32
#define BATCH    8
#define NODES    32
#define MSTR     33               // m-stride in G/W2 (and row stride in P2)
#define ISTR     1058             // i-stride = 32*33+2 (mod 32 == 2)
#define GSZ      (NLAT * ISTR)    // 10580 floats per array
#define TMAIN    512

// Scratch (static __device__ arrays: no dynamic allocation allowed)
__device__ float g_encoded[BATCH * NLAT];                 // bias pre-added
__device__ __align__(128) float g_dec4[N_FULL * 16];      // 64B rows [v0..v9,pad6]

// ---------------------------------------------------------------------------
// Kernel 1 (fused): blocks 0..79 compute encoded[b,i] + enc_b[i] directly.
// Blocks 80..275 transpose decoder [n,N] -> [N,16] (64B-aligned rows).
// ---------------------------------------------------------------------------
__global__ void __launch_bounds__(256)
prep_encode_kernel(const float* __restrict__ x,
                   const float* __restrict__ ew,
                   const float* __restrict__ enc_b,
                   const float* __restrict__ decoder) {
    if (blockIdx.x < BATCH * NLAT) {
        const int b = blockIdx.x / NLAT;
        const int i = blockIdx.x % NLAT;
        const float4* xr = (const float4*)(x  + (size_t)b * N_FULL);
        const float4* wr = (const float4*)(ew + (size_t)i * N_FULL);
        float acc = 0.0f;
        for (int t = threadIdx.x; t < N_FULL / 4; t += 256) {
            float4 a = __ldg(xr + t);
            float4 c = __ldg(wr + t);
            acc = fmaf(a.x, c.x, acc);
            acc = fmaf(a.y, c.y, acc);
            acc = fmaf(a.z, c.z, acc);
            acc = fmaf(a.w, c.w, acc);
        }
#pragma unroll
        for (int d = 16; d > 0; d >>= 1)
            acc += __shfl_xor_sync(0xffffffffu, acc, d);
        __shared__ float red[8];
        int lane = threadIdx.x & 31, warp = threadIdx.x >> 5;
        if (lane == 0) red[warp] = acc;
        __syncthreads();
        if (threadIdx.x == 0) {
            float s = 0.0f;
#pragma unroll
            for (int w = 0; w < 8; w++) s += red[w];
            g_encoded[blockIdx.x] = s + __ldg(enc_b + i);   // bias folded in
        }
    } else {
        int p = (blockIdx.x - BATCH * NLAT) * 256 + threadIdx.x;
        if (p < N_FULL) {
            float v[NLAT];
#pragma unroll
            for (int i = 0; i < NLAT; i++)
                v[i] = __ldg(decoder + (size_t)i * N_FULL + p);
            float4* dst = (float4*)(g_dec4 + (size_t)p * 16);
            dst[0] = make_float4(v[0], v[1], v[2], v[3]);
            dst[1] = make_float4(v[4], v[5], v[6], v[7]);
            dst[2] = make_float4(v[8], v[9], 0.0f, 0.0f);
            dst[3] = make_float4(0.0f, 0.0f, 0.0f, 0.0f);
        }
    }
}

// ---------------------------------------------------------------------------
// Kernel 2: main. 512 threads (16 warps), 32 nodes/block, 2 CTAs/SM.
// (Same as R8, launched WITHOUT PDL: plain sequential graph nodes.)
//
//  Entry: warps 0..9 prefetch their 10 bw values into registers; the
//    neighbour tile goes to smem. Latency overlaps the gather via scoreboard.
//  Phase A (gather): 4 lanes per 64B decoder row; one warp-LDG = 8 random
//    rows = 8 line-touches -> 1 L1 wavefront per neighbour row.
//    Scatter banks (8q+2u+m+j)%32: conflict-free.
//  Phase B (scan): warps 0..9, task (i=warp, j=lane): G <- prefix(g),
//    W2 <- prefix(m^2 g) over m. Banks (2i+m+j)%32: conflict-free.
//  Phase C: warp = i (10 warps), lane = j. z[b] = sum_k bwv[k]*enc[k][b]
//    computed ONCE per (i,p) for all 8 batches (enc via broadcast LDS.128)
//    -> 100 bw LDG/CTA instead of 800. Closed-form window:
//      smoothed = (Pg[cnt-1] - inv2*Pm2[cnt-1]) / (cnt - inv2*S2(cnt));
//    contribution enc[b,i]*smv parked in P2[b][i][j].
//  Combine: warps 0..7 (b = warp) sum P2 over i, store out[b,p].
// ---------------------------------------------------------------------------
__global__ void __launch_bounds__(TMAIN, 2)
main_kernel(const float* __restrict__ bw,
            const int*   __restrict__ neigh,
            float*       __restrict__ out) {
    extern __shared__ float sm[];
    float*          G    = sm;                         // [GSZ]
    float*          W2   = sm + GSZ;                   // [GSZ]
    float*          P2   = sm + 2 * GSZ;               // [8][10][33]
    float*          encS = P2 + BATCH * NLAT * MSTR;   // [10][8]  (k-major)
    unsigned short* NB   = (unsigned short*)(encS + BATCH * NLAT);  // [1024]

    const int tid    = threadIdx.x;
    const int lane   = tid & 31;
    const int warp   = tid >> 5;
    const int p_base = blockIdx.x * NODES;
    const int p      = p_base + lane;
    const int pc     = (p < N_FULL) ? p : (N_FULL - 1);

    // ---- prefetch: neighbour tile + per-warp bw values ----
    {
        int base = p_base * MU + tid * 2;
        int2 v = make_int2(0, 0);
        if (base + 1 < N_FULL * MU) v = *(const int2*)(neigh + base);
        NB[tid * 2 + 0] = (unsigned short)v.x;
        NB[tid * 2 + 1] = (unsigned short)v.y;
    }
    float bwv[NLAT];                     // bw[i=warp, k, pc], warps 0..9
    if (warp < NLAT) {
#pragma unroll
        for (int k = 0; k < NLAT; k++)
            bwv[k] = __ldg(bw + (size_t)(warp * NLAT + k) * N_FULL + pc);
    }
    // encoded tile -> smem, k-major: encS[k*8+b]
    if (tid < BATCH * NLAT)
        encS[tid] = g_encoded[(tid & 7) * NLAT + (tid >> 3)];
    __syncthreads();

    // ---- Phase A: cooperative gather (64 rows/warp, 8 rows per LDG) ----
    {
        const int q  = lane & 3;         // 16B quarter of the 64B row
        const int rl = lane >> 2;        // row-in-instruction 0..7
#pragma unroll
        for (int t = 0; t < 8; t++) {
            const int r = warp * 64 + t * 8 + rl;   // flat row: j=r>>5, m=r&31
            const int m = r & 31;
            const int j = r >> 5;
            const int nb = NB[r];
            if (q < 3) {
                float4 v = __ldg((const float4*)g_dec4 + nb * 4 + q);
                const int a0 = (4 * q) * ISTR + m * MSTR + j;
                G[a0] = v.x;
                G[a0 + ISTR] = v.y;
                if (q < 2) {
                    G[a0 + 2 * ISTR] = v.z;
                    G[a0 + 3 * ISTR] = v.w;
                }
            }
        }
    }
    __syncthreads();

    // ---- Phase B: inclusive prefix over m (warps 0..9: i = warp, j = lane)
    if (tid < NLAT * NODES) {
        const int base = warp * ISTR + lane;
        float pg = 0.0f, pm = 0.0f;
#pragma unroll
        for (int m = 0; m < MU; m++) {
            float v = G[base + m * MSTR];
            pg += v;
            pm = fmaf((float)(m * m), v, pm);
            G [base + m * MSTR] = pg;
            W2[base + m * MSTR] = pm;
        }
    }
    __syncthreads();

    // ---- Phase C: warp = i, lane = j; all 8 batches per thread ----
    if (warp < NLAT) {
        const int i = warp;
        const int j = lane;

        float z[BATCH];
#pragma unroll
        for (int b = 0; b < BATCH; b++) z[b] = 0.0f;
#pragma unroll
        for (int k = 0; k < NLAT; k++) {
            float4 e0 = *(const float4*)(encS + k * 8);      // broadcast LDS
            float4 e1 = *(const float4*)(encS + k * 8 + 4);
            z[0] = fmaf(bwv[k], e0.x, z[0]);
            z[1] = fmaf(bwv[k], e0.y, z[1]);
            z[2] = fmaf(bwv[k], e0.z, z[2]);
            z[3] = fmaf(bwv[k], e0.w, z[3]);
            z[4] = fmaf(bwv[k], e1.x, z[4]);
            z[5] = fmaf(bwv[k], e1.y, z[5]);
            z[6] = fmaf(bwv[k], e1.z, z[6]);
            z[7] = fmaf(bwv[k], e1.w, z[7]);
        }

#pragma unroll
        for (int b = 0; b < BATCH; b++) {
            float e    = __expf(-z[b]);
            float tt   = 1.0f + e;                              // = 1/w
            float u    = __fdividef((float)MU, tt);             // = MU*w
            int   cnt  = min(MU, (int)u + 1);                   // #active m
            float inv2 = tt * tt * (1.0f / (float)(MU * MU));   // 1/(MU*w)^2

            const int base = i * ISTR + (cnt - 1) * MSTR + j;
            float Pg = G[base];
            float Pm = W2[base];
            int   c1 = cnt - 1;
            float S2 = (float)(c1 * cnt * (2 * cnt - 1)) * (1.0f / 6.0f);
            float s  = (float)cnt - inv2 * S2;
            float smv = __fdividef(fmaf(-inv2, Pm, Pg), s);
            P2[(b * NLAT + i) * MSTR + j] = encS[i * 8 + b] * smv;
        }
    }
    __syncthreads();

    // ---- Combine: warp = b (8 warps), lane = j: sum over i, store ----
    if (warp < BATCH && p < N_FULL) {
        float acc = 0.0f;
#pragma unroll
        for (int i = 0; i < NLAT; i++)
            acc += P2[(warp * NLAT + i) * MSTR + lane];
        out[(size_t)warp * N_FULL + p] = acc;
    }
}

// ---------------------------------------------------------------------------
extern "C" void kernel_launch(void* const* d_in, const int* in_sizes, int n_in,
                              void* d_out, int out_size) {
    const float* x       = (const float*)d_in[0];
    const float* enc_w   = (const float*)d_in[1];
    const float* enc_b   = (const float*)d_in[2];
    const float* decoder = (const float*)d_in[3];
    const float* bw      = (const float*)d_in[4];
    const int*   neigh   = (const int*)  d_in[5];
    float*       out     = (float*)d_out;
    (void)in_sizes; (void)n_in; (void)out_size;

    const int tp_blocks = (N_FULL + 255) / 256;                 // 196
    prep_encode_kernel<<<BATCH * NLAT + tp_blocks, 256>>>(x, enc_w, enc_b,
                                                          decoder);

    size_t smem_bytes = (size_t)(2 * GSZ + BATCH * NLAT * MSTR + BATCH * NLAT)
                        * sizeof(float)
                      + (size_t)(NODES * MU) * sizeof(unsigned short);
    cudaFuncSetAttribute(main_kernel,
                         cudaFuncAttributeMaxDynamicSharedMemorySize,
                         (int)smem_bytes);

    // Plain launch (no PDL): sequential graph nodes.
    main_kernel<<<(N_FULL + NODES - 1) / NODES, TMAIN, smem_bytes>>>(
        bw, neigh, out);
}

// round 10
// speedup vs baseline: 1.0963x; 1.0059x over previous
#include <cuda_runtime.h>

#define N_FULL   50000
#define NLAT     10
#define MU       32
#define BATCH    8
#define NODES    32
#define MSTR     33               // m-stride in G/W2 (and row stride in P2)
#define ISTR     1058             // i-stride = 32*33+2 (mod 32 == 2)
#define GSZ      (NLAT * ISTR)    // 10580 floats per array
#define TMAIN    512

// smem float offsets
#define OFF_G     0
#define OFF_W2    10580
#define OFF_P2    21160            // [8][10][33] = 2640
#define OFF_ENCS  23800            // [10][8] k-major = 80
#define OFF_INV2  23880            // [10][8][32] = 2560
#define OFF_RMAX  26440            // int[32]
#define OFF_NB    26472            // ushort[1024]
#define SMEM_FLOATS (OFF_NB)
#define SMEM_BYTES  (OFF_NB * 4 + NODES * MU * 2)   // 107,936 B

// Scratch (static __device__ arrays: no dynamic allocation allowed)
__device__ float g_encoded[BATCH * NLAT];                 // bias pre-added
__device__ __align__(128) float g_dec4[N_FULL * 16];      // 64B rows [v0..v9,pad6]

// ---------------------------------------------------------------------------
// Kernel 1 (fused): blocks 0..79 compute encoded[b,i] + enc_b[i] directly.
// Blocks 80..275 transpose decoder [n,N] -> [N,16] (64B-aligned rows).
// ---------------------------------------------------------------------------
__global__ void __launch_bounds__(256)
prep_encode_kernel(const float* __restrict__ x,
                   const float* __restrict__ ew,
                   const float* __restrict__ enc_b,
                   const float* __restrict__ decoder) {
    if (blockIdx.x < BATCH * NLAT) {
        const int b = blockIdx.x / NLAT;
        const int i = blockIdx.x % NLAT;
        const float4* xr = (const float4*)(x  + (size_t)b * N_FULL);
        const float4* wr = (const float4*)(ew + (size_t)i * N_FULL);
        float acc = 0.0f;
        for (int t = threadIdx.x; t < N_FULL / 4; t += 256) {
            float4 a = __ldg(xr + t);
            float4 c = __ldg(wr + t);
            acc = fmaf(a.x, c.x, acc);
            acc = fmaf(a.y, c.y, acc);
            acc = fmaf(a.z, c.z, acc);
            acc = fmaf(a.w, c.w, acc);
        }
#pragma unroll
        for (int d = 16; d > 0; d >>= 1)
            acc += __shfl_xor_sync(0xffffffffu, acc, d);
        __shared__ float red[8];
        int lane = threadIdx.x & 31, warp = threadIdx.x >> 5;
        if (lane == 0) red[warp] = acc;
        __syncthreads();
        if (threadIdx.x == 0) {
            float s = 0.0f;
#pragma unroll
            for (int w = 0; w < 8; w++) s += red[w];
            g_encoded[blockIdx.x] = s + __ldg(enc_b + i);   // bias folded in
        }
    } else {
        int p = (blockIdx.x - BATCH * NLAT) * 256 + threadIdx.x;
        if (p < N_FULL) {
            float v[NLAT];
#pragma unroll
            for (int i = 0; i < NLAT; i++)
                v[i] = __ldg(decoder + (size_t)i * N_FULL + p);
            float4* dst = (float4*)(g_dec4 + (size_t)p * 16);
            dst[0] = make_float4(v[0], v[1], v[2], v[3]);
            dst[1] = make_float4(v[4], v[5], v[6], v[7]);
            dst[2] = make_float4(v[8], v[9], 0.0f, 0.0f);
            dst[3] = make_float4(0.0f, 0.0f, 0.0f, 0.0f);
        }
    }
}

// ---------------------------------------------------------------------------
// Kernel 2: main. 512 threads, 32 nodes/block, 2 CTAs/SM.
//
//  Phase 0 (warps 0..9, warp=i, lane=j): z[b] for all 8 batches, then
//    cnt/inv2 per b; inv2 stored to smem; rowmax[j] = max(cnt)+1 via
//    smem atomicMax. Typical cnt~17 -> rowmax ~19: the upper ~40% of the
//    neighbour window is provably untouched by ANY (b,i) at this node.
//  Phase A (gather, all 16 warps): only rows m < rowmax[j]; whole 8-row
//    blocks skipped warp-uniformly, remainder per-row predicated.
//    1 L1 wavefront per gathered row (4 lanes per 64B decoder row).
//  Phase B (scan, all 16 warps, 20 tasks each): prefix to rowmax[j] only.
//  Phase C (warps 0..9): cnt recomputed as floor(rsqrt(inv2))+1 (<=1 off
//    near integer u; covered by the +1 rowmax guard, marginal weight ~0).
//    Closed-form window:
//      smoothed = (Pg[cnt-1] - inv2*Pm2[cnt-1]) / (cnt - inv2*S2(cnt));
//    contribution enc[b,i]*smv parked in P2[b][i][j].
//  Combine: warps 0..7 (b=warp) sum P2 over i, store out[b,p].
// ---------------------------------------------------------------------------
__global__ void __launch_bounds__(TMAIN, 2)
main_kernel(const float* __restrict__ bw,
            const int*   __restrict__ neigh,
            float*       __restrict__ out) {
    extern __shared__ float sm[];
    float*          G     = sm + OFF_G;
    float*          W2    = sm + OFF_W2;
    float*          P2    = sm + OFF_P2;
    float*          encS  = sm + OFF_ENCS;
    float*          sInv2 = sm + OFF_INV2;
    int*            rmax  = (int*)(sm + OFF_RMAX);
    unsigned short* NB    = (unsigned short*)(sm + OFF_NB);

    const int tid    = threadIdx.x;
    const int lane   = tid & 31;
    const int warp   = tid >> 5;
    const int p_base = blockIdx.x * NODES;
    const int p      = p_base + lane;
    const int pc     = (p < N_FULL) ? p : (N_FULL - 1);

    // ---- entry: neighbour tile, bw prefetch, encoded tile, rowmax init ----
    {
        int base = p_base * MU + tid * 2;
        int2 v = make_int2(0, 0);
        if (base + 1 < N_FULL * MU) v = *(const int2*)(neigh + base);
        NB[tid * 2 + 0] = (unsigned short)v.x;
        NB[tid * 2 + 1] = (unsigned short)v.y;
    }
    float bwv[NLAT];                     // bw[i=warp, k, pc], warps 0..9
    if (warp < NLAT) {
#pragma unroll
        for (int k = 0; k < NLAT; k++)
            bwv[k] = __ldg(bw + (size_t)(warp * NLAT + k) * N_FULL + pc);
    }
    if (tid < BATCH * NLAT)              // encS[k*8+b]
        encS[tid] = g_encoded[(tid & 7) * NLAT + (tid >> 3)];
    if (tid < NODES) rmax[tid] = 0;
    __syncthreads();

    // ---- Phase 0: z -> (inv2, cnt); rowmax[j] (warps 0..9) ----
    if (warp < NLAT) {
        const int i = warp, j = lane;
        float z[BATCH];
#pragma unroll
        for (int b = 0; b < BATCH; b++) z[b] = 0.0f;
#pragma unroll
        for (int k = 0; k < NLAT; k++) {
            float4 e0 = *(const float4*)(encS + k * 8);
            float4 e1 = *(const float4*)(encS + k * 8 + 4);
            z[0] = fmaf(bwv[k], e0.x, z[0]);
            z[1] = fmaf(bwv[k], e0.y, z[1]);
            z[2] = fmaf(bwv[k], e0.z, z[2]);
            z[3] = fmaf(bwv[k], e0.w, z[3]);
            z[4] = fmaf(bwv[k], e1.x, z[4]);
            z[5] = fmaf(bwv[k], e1.y, z[5]);
            z[6] = fmaf(bwv[k], e1.z, z[6]);
            z[7] = fmaf(bwv[k], e1.w, z[7]);
        }
        int cmax = 0;
#pragma unroll
        for (int b = 0; b < BATCH; b++) {
            float e    = __expf(-z[b]);
            float tt   = 1.0f + e;                              // = 1/w
            float u    = __fdividef((float)MU, tt);             // = MU*w
            int   cnt  = min(MU, (int)u + 1);
            float inv2 = tt * tt * (1.0f / (float)(MU * MU));   // 1/(MU*w)^2
            sInv2[(i * 8 + b) * 32 + j] = inv2;
            cmax = max(cmax, cnt);
        }
        atomicMax(&rmax[j], min(MU, cmax + 1));   // +1 ulp guard for phase C
    }
    __syncthreads();

    // ---- Phase A: gather rows m < rowmax[j] (all 16 warps) ----
    {
        const int q  = lane & 3;         // 16B quarter of the 64B row
        const int rl = lane >> 2;        // row-in-instruction 0..7
#pragma unroll
        for (int half = 0; half < 2; half++) {
            const int j  = warp * 2 + half;
            const int rm = rmax[j];                  // warp-uniform
#pragma unroll
            for (int t4 = 0; t4 < 4; t4++) {
                if (t4 * 8 >= rm) break;             // warp-uniform skip
                const int m = t4 * 8 + rl;
                if (m < rm && q < 3) {
                    const int nb = NB[j * MU + m];
                    float4 v = __ldg((const float4*)g_dec4 + nb * 4 + q);
                    const int a0 = (4 * q) * ISTR + m * MSTR + j;
                    G[a0] = v.x;
                    G[a0 + ISTR] = v.y;
                    if (q < 2) {
                        G[a0 + 2 * ISTR] = v.z;
                        G[a0 + 3 * ISTR] = v.w;
                    }
                }
            }
        }
    }
    __syncthreads();

    // ---- Phase B: prefix over m < rowmax[j] (all 16 warps, 20 tasks each) --
    if (lane < 20) {
        const int t = warp * 20 + lane;              // 0..319
        const int i = t >> 5;
        const int j = t & 31;
        const int mlim = rmax[j];
        const int base = i * ISTR + j;
        float pg = 0.0f, pm = 0.0f;
        for (int m = 0; m < mlim; m++) {
            float v = G[base + m * MSTR];
            pg += v;
            pm = fmaf((float)(m * m), v, pm);
            G [base + m * MSTR] = pg;
            W2[base + m * MSTR] = pm;
        }
    }
    __syncthreads();

    // ---- Phase C: warp = i, lane = j; all 8 batches per thread ----
    if (warp < NLAT) {
        const int i = warp, j = lane;
#pragma unroll
        for (int b = 0; b < BATCH; b++) {
            float inv2 = sInv2[(i * 8 + b) * 32 + j];
            float u    = rsqrtf(inv2);                          // = MU*w
            int   cnt  = min(MU, (int)u + 1);                   // <= rmax[j]

            const int base = i * ISTR + (cnt - 1) * MSTR + j;
            float Pg = G[base];
            float Pm = W2[base];
            int   c1 = cnt - 1;
            float S2 = (float)(c1 * cnt * (2 * cnt - 1)) * (1.0f / 6.0f);
            float s  = (float)cnt - inv2 * S2;
            float smv = __fdividef(fmaf(-inv2, Pm, Pg), s);
            P2[(b * NLAT + i) * MSTR + j] = encS[i * 8 + b] * smv;
        }
    }
    __syncthreads();

    // ---- Combine: warp = b (8 warps), lane = j: sum over i, store ----
    if (warp < BATCH && p < N_FULL) {
        float acc = 0.0f;
#pragma unroll
        for (int i = 0; i < NLAT; i++)
            acc += P2[(warp * NLAT + i) * MSTR + lane];
        out[(size_t)warp * N_FULL + p] = acc;
    }
}

// ---------------------------------------------------------------------------
extern "C" void kernel_launch(void* const* d_in, const int* in_sizes, int n_in,
                              void* d_out, int out_size) {
    const float* x       = (const float*)d_in[0];
    const float* enc_w   = (const float*)d_in[1];
    const float* enc_b   = (const float*)d_in[2];
    const float* decoder = (const float*)d_in[3];
    const float* bw      = (const float*)d_in[4];
    const int*   neigh   = (const int*)  d_in[5];
    float*       out     = (float*)d_out;
    (void)in_sizes; (void)n_in; (void)out_size;

    const int tp_blocks = (N_FULL + 255) / 256;                 // 196
    prep_encode_kernel<<<BATCH * NLAT + tp_blocks, 256>>>(x, enc_w, enc_b,
                                                          decoder);

    cudaFuncSetAttribute(main_kernel,
                         cudaFuncAttributeMaxDynamicSharedMemorySize,
                         SMEM_BYTES);
    main_kernel<<<(N_FULL + NODES - 1) / NODES, TMAIN, SMEM_BYTES>>>(
        bw, neigh, out);
}

// round 13
// speedup vs baseline: 1.2034x; 1.0977x over previous
#include <cuda_runtime.h>

#define N_FULL   50000
#define NLAT     10
#define MU       32
#define BATCH    8
#define NODES    32
#define MSTR     33               // m-stride in G/W2 (and row stride in P2)
#define ISTR     1058             // i-stride = 32*33+2 (mod 32 == 2)
#define GSZ      (NLAT * ISTR)    // 10580 floats per array
#define TMAIN    512
#define TPREP    512

// smem float offsets (main)
#define OFF_G     0
#define OFF_W2    10580
#define OFF_P2    21160            // [8][10][33] = 2640
#define OFF_ENCS  23800            // [10][8] k-major = 80
#define OFF_INV2  23880            // [10][8][32] = 2560
#define OFF_RMAX  26440            // int[32]
#define OFF_NB    26472            // ushort[1024]
#define SMEM_BYTES  (OFF_NB * 4 + NODES * MU * 2)   // 107,936 B

// Scratch (static __device__ arrays: no dynamic allocation allowed)
__device__ float g_encoded[BATCH * NLAT];                 // bias pre-added
__device__ __align__(128) float g_dec4[N_FULL * 16];      // 64B rows [v0..v9,pad6]

// ---------------------------------------------------------------------------
// Kernel 1 (fused, 512 threads): blocks 0..79 compute encoded[b,i]+enc_b[i]
// directly (25 float4 iters, unrolled for MLP). Blocks 80..177 transpose
// decoder [n,N] -> [N,16] (64B-aligned rows), 512 nodes per block.
// ---------------------------------------------------------------------------
__global__ void __launch_bounds__(TPREP)
prep_encode_kernel(const float* __restrict__ x,
                   const float* __restrict__ ew,
                   const float* __restrict__ enc_b,
                   const float* __restrict__ decoder) {
    if (blockIdx.x < BATCH * NLAT) {
        const int b = blockIdx.x / NLAT;
        const int i = blockIdx.x % NLAT;
        const float4* xr = (const float4*)(x  + (size_t)b * N_FULL);
        const float4* wr = (const float4*)(ew + (size_t)i * N_FULL);
        float acc = 0.0f;
#pragma unroll 4
        for (int t = threadIdx.x; t < N_FULL / 4; t += TPREP) {
            float4 a = __ldg(xr + t);
            float4 c = __ldg(wr + t);
            acc = fmaf(a.x, c.x, acc);
            acc = fmaf(a.y, c.y, acc);
            acc = fmaf(a.z, c.z, acc);
            acc = fmaf(a.w, c.w, acc);
        }
#pragma unroll
        for (int d = 16; d > 0; d >>= 1)
            acc += __shfl_xor_sync(0xffffffffu, acc, d);
        __shared__ float red[16];
        int lane = threadIdx.x & 31, warp = threadIdx.x >> 5;
        if (lane == 0) red[warp] = acc;
        __syncthreads();
        if (threadIdx.x == 0) {
            float s = 0.0f;
#pragma unroll
            for (int w = 0; w < 16; w++) s += red[w];
            g_encoded[blockIdx.x] = s + __ldg(enc_b + i);   // bias folded in
        }
    } else {
        int p = (blockIdx.x - BATCH * NLAT) * TPREP + threadIdx.x;
        if (p < N_FULL) {
            float v[NLAT];
#pragma unroll
            for (int i = 0; i < NLAT; i++)
                v[i] = __ldg(decoder + (size_t)i * N_FULL + p);
            float4* dst = (float4*)(g_dec4 + (size_t)p * 16);
            dst[0] = make_float4(v[0], v[1], v[2], v[3]);
            dst[1] = make_float4(v[4], v[5], v[6], v[7]);
            dst[2] = make_float4(v[8], v[9], 0.0f, 0.0f);
            dst[3] = make_float4(0.0f, 0.0f, 0.0f, 0.0f);
        }
    }
}

// ---------------------------------------------------------------------------
// Kernel 2: main. 512 threads, 32 nodes/block, 2 CTAs/SM.
//
//  Phase 0 (warps 0..9, warp=i, lane=j): z[b] for 8 batches; inv2 -> smem;
//    rowmax[j] = max(cnt)+1 via smem atomicMax (typ. ~19 of 32).
//  Phase A (gather, 16 warps): rows m < rowmax[j] only; 4 lanes per 64B
//    decoder row -> 1 L1 wavefront per gathered row.
//  Phase B (scan, warps 0..9, warp=i, lane=j): FULLY-UNROLLED branch-free
//    32-iter prefix (G <- prefix(g), W2 <- prefix(m^2 g)). Garbage beyond
//    rowmax[j] is never read (cnt-1 < rowmax). The unrolled form lets ptxas
//    batch the 32 LDS (high MLP) -> serial chain ~32 FMA instead of 19
//    latency-exposed LDS round trips.
//  Phase C (warps 0..9): cnt = floor(rsqrt(inv2))+1 (+1-guard in rowmax);
//      smoothed = (Pg[cnt-1] - inv2*Pm2[cnt-1]) / (cnt - inv2*S2(cnt));
//    contribution enc[b,i]*smv parked in P2[b][i][j].
//  Combine: warps 0..7 (b=warp) sum P2 over i, store out[b,p].
// ---------------------------------------------------------------------------
__global__ void __launch_bounds__(TMAIN, 2)
main_kernel(const float* __restrict__ bw,
            const int*   __restrict__ neigh,
            float*       __restrict__ out) {
    extern __shared__ float sm[];
    float*          G     = sm + OFF_G;
    float*          W2    = sm + OFF_W2;
    float*          P2    = sm + OFF_P2;
    float*          encS  = sm + OFF_ENCS;
    float*          sInv2 = sm + OFF_INV2;
    int*            rmax  = (int*)(sm + OFF_RMAX);
    unsigned short* NB    = (unsigned short*)(sm + OFF_NB);

    const int tid    = threadIdx.x;
    const int lane   = tid & 31;
    const int warp   = tid >> 5;
    const int p_base = blockIdx.x * NODES;
    const int p      = p_base + lane;
    const int pc     = (p < N_FULL) ? p : (N_FULL - 1);

    // ---- entry: neighbour tile, bw prefetch, encoded tile, rowmax init ----
    {
        int base = p_base * MU + tid * 2;
        int2 v = make_int2(0, 0);
        if (base + 1 < N_FULL * MU) v = *(const int2*)(neigh + base);
        NB[tid * 2 + 0] = (unsigned short)v.x;
        NB[tid * 2 + 1] = (unsigned short)v.y;
    }
    float bwv[NLAT];                     // bw[i=warp, k, pc], warps 0..9
    if (warp < NLAT) {
#pragma unroll
        for (int k = 0; k < NLAT; k++)
            bwv[k] = __ldg(bw + (size_t)(warp * NLAT + k) * N_FULL + pc);
    }
    if (tid < BATCH * NLAT)              // encS[k*8+b]
        encS[tid] = g_encoded[(tid & 7) * NLAT + (tid >> 3)];
    if (tid < NODES) rmax[tid] = 0;
    __syncthreads();

    // ---- Phase 0: z -> (inv2, cnt); rowmax[j] (warps 0..9) ----
    if (warp < NLAT) {
        const int i = warp, j = lane;
        float z[BATCH];
#pragma unroll
        for (int b = 0; b < BATCH; b++) z[b] = 0.0f;
#pragma unroll
        for (int k = 0; k < NLAT; k++) {
            float4 e0 = *(const float4*)(encS + k * 8);
            float4 e1 = *(const float4*)(encS + k * 8 + 4);
            z[0] = fmaf(bwv[k], e0.x, z[0]);
            z[1] = fmaf(bwv[k], e0.y, z[1]);
            z[2] = fmaf(bwv[k], e0.z, z[2]);
            z[3] = fmaf(bwv[k], e0.w, z[3]);
            z[4] = fmaf(bwv[k], e1.x, z[4]);
            z[5] = fmaf(bwv[k], e1.y, z[5]);
            z[6] = fmaf(bwv[k], e1.z, z[6]);
            z[7] = fmaf(bwv[k], e1.w, z[7]);
        }
        int cmax = 0;
#pragma unroll
        for (int b = 0; b < BATCH; b++) {
            float e    = __expf(-z[b]);
            float tt   = 1.0f + e;                              // = 1/w
            float u    = __fdividef((float)MU, tt);             // = MU*w
            int   cnt  = min(MU, (int)u + 1);
            float inv2 = tt * tt * (1.0f / (float)(MU * MU));   // 1/(MU*w)^2
            sInv2[(i * 8 + b) * 32 + j] = inv2;
            cmax = max(cmax, cnt);
        }
        atomicMax(&rmax[j], min(MU, cmax + 1));   // +1 ulp guard for phase C
    }
    __syncthreads();

    // ---- Phase A: gather rows m < rowmax[j] (all 16 warps) ----
    {
        const int q  = lane & 3;         // 16B quarter of the 64B row
        const int rl = lane >> 2;        // row-in-instruction 0..7
#pragma unroll
        for (int half = 0; half < 2; half++) {
            const int j  = warp * 2 + half;
            const int rm = rmax[j];                  // warp-uniform
#pragma unroll
            for (int t4 = 0; t4 < 4; t4++) {
                if (t4 * 8 >= rm) break;             // warp-uniform skip
                const int m = t4 * 8 + rl;
                if (m < rm && q < 3) {
                    const int nb = NB[j * MU + m];
                    float4 v = __ldg((const float4*)g_dec4 + nb * 4 + q);
                    const int a0 = (4 * q) * ISTR + m * MSTR + j;
                    G[a0] = v.x;
                    G[a0 + ISTR] = v.y;
                    if (q < 2) {
                        G[a0 + 2 * ISTR] = v.z;
                        G[a0 + 3 * ISTR] = v.w;
                    }
                }
            }
        }
    }
    __syncthreads();

    // ---- Phase B: branch-free fully-unrolled prefix (warps 0..9) ----
    // Values at m >= rowmax[j] are stale garbage but are never read in
    // phase C (cnt-1 < rowmax[j]); unrolling lets the 32 LDS batch up.
    if (warp < NLAT) {
        const int base = warp * ISTR + lane;         // i = warp, j = lane
        float pg = 0.0f, pm = 0.0f;
#pragma unroll
        for (int m = 0; m < MU; m++) {
            float v = G[base + m * MSTR];
            pg += v;
            pm = fmaf((float)(m * m), v, pm);
            G [base + m * MSTR] = pg;
            W2[base + m * MSTR] = pm;
        }
    }
    __syncthreads();

    // ---- Phase C: warp = i, lane = j; all 8 batches per thread ----
    if (warp < NLAT) {
        const int i = warp, j = lane;
#pragma unroll
        for (int b = 0; b < BATCH; b++) {
            float inv2 = sInv2[(i * 8 + b) * 32 + j];
            float u    = rsqrtf(inv2);                          // = MU*w
            int   cnt  = min(MU, (int)u + 1);                   // <= rmax[j]

            const int base = i * ISTR + (cnt - 1) * MSTR + j;
            float Pg = G[base];
            float Pm = W2[base];
            int   c1 = cnt - 1;
            float S2 = (float)(c1 * cnt * (2 * cnt - 1)) * (1.0f / 6.0f);
            float s  = (float)cnt - inv2 * S2;
            float smv = __fdividef(fmaf(-inv2, Pm, Pg), s);
            P2[(b * NLAT + i) * MSTR + j] = encS[i * 8 + b] * smv;
        }
    }
    __syncthreads();

    // ---- Combine: warp = b (8 warps), lane = j: sum over i, store ----
    if (warp < BATCH && p < N_FULL) {
        float acc = 0.0f;
#pragma unroll
        for (int i = 0; i < NLAT; i++)
            acc += P2[(warp * NLAT + i) * MSTR + lane];
        out[(size_t)warp * N_FULL + p] = acc;
    }
}

// ---------------------------------------------------------------------------
extern "C" void kernel_launch(void* const* d_in, const int* in_sizes, int n_in,
                              void* d_out, int out_size) {
    const float* x       = (const float*)d_in[0];
    const float* enc_w   = (const float*)d_in[1];
    const float* enc_b   = (const float*)d_in[2];
    const float* decoder = (const float*)d_in[3];
    const float* bw      = (const float*)d_in[4];
    const int*   neigh   = (const int*)  d_in[5];
    float*       out     = (float*)d_out;
    (void)in_sizes; (void)n_in; (void)out_size;

    const int tp_blocks = (N_FULL + TPREP - 1) / TPREP;         // 98
    prep_encode_kernel<<<BATCH * NLAT + tp_blocks, TPREP>>>(x, enc_w, enc_b,
                                                            decoder);

    cudaFuncSetAttribute(main_kernel,
                         cudaFuncAttributeMaxDynamicSharedMemorySize,
                         SMEM_BYTES);
    main_kernel<<<(N_FULL + NODES - 1) / NODES, TMAIN, SMEM_BYTES>>>(
        bw, neigh, out);
}